// round 7
// baseline (speedup 1.0000x reference)
#include <cuda_runtime.h>
#include <math.h>

#define Bb 32
#define Tt 8
#define Nn 150
#define Ff 16
#define Hh 32
#define Rr 4
#define Ee 16

#define NP 160
#define NR 192
#define HSZ (Bb*Nn*Hh*Rr)
#define SLOTSTR (NP*2048)          // slot stride in Hf/Gf

// Karatsuba slots: 0=f0, 1=Re f1, 2=Im f1, 3=f2, 4=slot1+slot2
// Mixed planes (consumption form): 0=m0, 1=Re(A@X f1), 2=Im(A@X f1), 3=m2
__device__ float g_At [5*NP*NR];          // A^T padded: At[s][k][n]
__device__ float g_W  [2*3*64*128];       // [l*3+gate][c][h][mix4] (float4 per (c,h))
__device__ float g_Xf [5*Tt*NP*512];      // slot fft of X
__device__ float g_AXt[4*Tt*Nn*512];      // MIXED A@fft(X), all t
__device__ float g_Hf [5*NP*2048];        // slots of H; col = b*64 + layer*32 + c
__device__ float g_Gf [5*NP*2048];        // slots of Rg*Hs; same layout
__device__ float g_AH0[4*Nn*1024];        // MIXED A@fft(H0_prev); [m][n][b*32+c]
__device__ float g_Z  [2*HSZ];
__device__ float g_H  [4*HSZ];

// ---------------------------------------------------------------------------
__global__ void adj_kernel(const float* __restrict__ U) {
    __shared__ float sUf[Ee][4];
    __shared__ float red[256];
    int n = blockIdx.x;
    int tid = threadIdx.x;
    if (tid < Ee*4) {
        int e = tid >> 2, s = tid & 3;
        const float* p = U + (n*Ee + e)*4;
        float u0=p[0],u1=p[1],u2=p[2],u3=p[3];
        float v;
        if (s==0) v = u0+u1+u2+u3;
        else if (s==1) v = u0-u2;
        else if (s==2) v = u3-u1;
        else v = u0-u1+u2-u3;
        sUf[e][s] = v;
    }
    __syncthreads();
    int m = tid;
    float a0=0.f,a1=0.f,a2=0.f,a3=0.f;
    if (m < Nn) {
        float P0=0.f,P1r=0.f,P1i=0.f,P2=0.f;
        #pragma unroll
        for (int e=0;e<Ee;e++){
            const float* p = U + (m*Ee + e)*4;
            float u0=p[0],u1=p[1],u2=p[2],u3=p[3];
            float m0=u0+u1+u2+u3, m1r=u0-u2, m1i=u3-u1, m2=u0-u1+u2-u3;
            float q0=sUf[e][0], q1r=sUf[e][1], q1i=sUf[e][2], q2=sUf[e][3];
            P0  += q0*m0;
            P2  += q2*m2;
            P1r += q1r*m1r - q1i*m1i;
            P1i += q1r*m1i + q1i*m1r;
        }
        a0 = fmaxf(0.25f*(P0 + P2 + 2.f*P1r), 0.f);
        a1 = fmaxf(0.25f*(P0 - P2 - 2.f*P1i), 0.f);
        a2 = fmaxf(0.25f*(P0 + P2 - 2.f*P1r), 0.f);
        a3 = fmaxf(0.25f*(P0 - P2 + 2.f*P1i), 0.f);
    }
    float av[4] = {a0,a1,a2,a3};
    float v[4];
    for (int r=0;r<4;r++){
        red[tid] = (m<Nn) ? av[r] : -1e30f; __syncthreads();
        for (int s=128;s>0;s>>=1){ if (tid<s) red[tid]=fmaxf(red[tid],red[tid+s]); __syncthreads(); }
        float mx = red[0]; __syncthreads();
        float ex = (m<Nn) ? expf(av[r]-mx) : 0.f;
        red[tid] = ex; __syncthreads();
        for (int s=128;s>0;s>>=1){ if (tid<s) red[tid]+=red[tid+s]; __syncthreads(); }
        float sm = red[0]; __syncthreads();
        v[r] = ex / sm;
    }
    if (m < Nn) {
        float s1 = v[0]-v[2];
        float s2 = v[3]-v[1];
        g_At[0*NP*NR + m*NR + n] = v[0]+v[1]+v[2]+v[3];
        g_At[1*NP*NR + m*NR + n] = s1;
        g_At[2*NP*NR + m*NR + n] = s2;
        g_At[3*NP*NR + m*NR + n] = v[0]-v[1]+v[2]-v[3];
        g_At[4*NP*NR + m*NR + n] = s1 + s2;
    }
}

// ---------------------------------------------------------------------------
__global__ void wprep_kernel(const float* wxz0,const float* wxr0,const float* wxh0,
                             const float* whz0,const float* whr0,
                             const float* wxz1,const float* wxr1,const float* wxh1,
                             const float* whz1,const float* whr1) {
    int idx = blockIdx.x*blockDim.x + threadIdx.x;
    if (idx >= 2*3*64*32) return;
    int h = idx & 31;
    int c = (idx >> 5) & 63;
    int g = (idx >> 11) % 3;
    int l = idx / (3*64*32);
    int Fin = l ? 32 : 16;
    int C = Fin + 32;
    float w[4] = {0.f,0.f,0.f,0.f};
    if (c < C) {
        bool xp = c < Fin;
        int row = xp ? c : (c - Fin);
        const float* src;
        if (l == 0)
            src = (g==0) ? (xp? wxz0: whz0) : (g==1) ? (xp? wxr0: whr0) : (xp? wxh0: whr0);
        else
            src = (g==0) ? (xp? wxz1: whz1) : (g==1) ? (xp? wxr1: whr1) : (xp? wxh1: whr1);
        const float* p = src + (row*Hh + h)*4;
        float u0=p[0],u1=p[1],u2=p[2],u3=p[3];
        w[0]=u0+u1+u2+u3; w[1]=u0-u2; w[2]=u3-u1; w[3]=u0-u1+u2-u3;
    }
    int base = ((l*3+g)*64 + c)*128 + h*4;
    #pragma unroll
    for (int s=0;s<4;s++) g_W[base + s] = w[s];
}

// ---------------------------------------------------------------------------
__global__ void xprep_kernel(const float* __restrict__ X){
    int idx = blockIdx.x*blockDim.x + threadIdx.x;
    if (idx >= Tt*Nn*512) return;
    int col = idx & 511;
    int rest = idx >> 9;
    int n = rest % Nn;
    int t = rest / Nn;
    int b = col >> 4, f = col & 15;
    const float4 v = *reinterpret_cast<const float4*>(
        X + ((((size_t)b*Tt + t)*Nn + n)*Ff + f)*4);
    float s1 = v.x - v.z, s2 = v.w - v.y;
    size_t base = ((size_t)t*NP + n)*512 + col;
    const size_t SS = (size_t)Tt*NP*512;
    g_Xf[0*SS + base] = v.x+v.y+v.z+v.w;
    g_Xf[1*SS + base] = s1;
    g_Xf[2*SS + base] = s2;
    g_Xf[3*SS + base] = v.x-v.y+v.z-v.w;
    g_Xf[4*SS + base] = s1 + s2;
}

// ---------------------------------------------------------------------------
// 32x64 5-slot aggregation tile -> MIXED 4-plane result in smem sH[4][32][64].
// stage: sA[2][32][32] + sB[2][32][64] = 6144 floats. K=160 in 5 chunks of 32.
// ---------------------------------------------------------------------------
__device__ __forceinline__ void aggTileMixed(
    float* stage, float* sH, int rt,
    const float* __restrict__ Bbase, int ldb, size_t sstB)
{
    float* sA = stage;
    float* sB = stage + 2048;
    int tid = threadIdx.x;
    int tx = tid & 15, ty = tid >> 4;
    int ar = tid >> 3, ac = (tid & 7)*4;
    int br = tid >> 4, bc = (tid & 15)*4;
    const float* AtBase = g_At + rt*32;

    float acc5[5][2][4];
    #pragma unroll
    for (int s=0;s<5;s++)
        #pragma unroll
        for (int i=0;i<2;i++)
            #pragma unroll
            for (int j=0;j<4;j++) acc5[s][i][j] = 0.f;

    #pragma unroll
    for (int s=0;s<5;s++){
        const float* Ap = AtBase + (size_t)s*NP*NR;
        const float* Bp = Bbase + (size_t)s*sstB;
        float4 ra  = *reinterpret_cast<const float4*>(Ap + (size_t)ar*NR + ac);
        float4 rb0 = *reinterpret_cast<const float4*>(Bp + (size_t)br*ldb + bc);
        float4 rb1 = *reinterpret_cast<const float4*>(Bp + (size_t)(br+16)*ldb + bc);
        *reinterpret_cast<float4*>(sA + 0*1024 + ar*32 + ac) = ra;
        *reinterpret_cast<float4*>(sB + 0*2048 + br*64 + bc) = rb0;
        *reinterpret_cast<float4*>(sB + 0*2048 + (br+16)*64 + bc) = rb1;
        __syncthreads();
        #pragma unroll
        for (int ch=0; ch<5; ch++){
            int buf = ch & 1;
            if (ch < 4){
                size_t ko = (size_t)(ch+1)*32;
                ra  = *reinterpret_cast<const float4*>(Ap + (ko+ar)*NR + ac);
                rb0 = *reinterpret_cast<const float4*>(Bp + (ko+br)*ldb + bc);
                rb1 = *reinterpret_cast<const float4*>(Bp + (ko+br+16)*ldb + bc);
            }
            #pragma unroll
            for (int k=0;k<32;k++){
                float a0 = sA[buf*1024 + k*32 + ty*2];
                float a1 = sA[buf*1024 + k*32 + ty*2 + 1];
                float4 b4 = *reinterpret_cast<const float4*>(sB + buf*2048 + k*64 + tx*4);
                float bv[4] = {b4.x, b4.y, b4.z, b4.w};
                #pragma unroll
                for (int j=0;j<4;j++){
                    acc5[s][0][j] += a0*bv[j];
                    acc5[s][1][j] += a1*bv[j];
                }
            }
            if (ch < 4){
                int nb = buf ^ 1;
                *reinterpret_cast<float4*>(sA + nb*1024 + ar*32 + ac) = ra;
                *reinterpret_cast<float4*>(sB + nb*2048 + br*64 + bc) = rb0;
                *reinterpret_cast<float4*>(sB + nb*2048 + (br+16)*64 + bc) = rb1;
            }
            __syncthreads();
        }
    }
    #pragma unroll
    for (int i=0;i<2;i++){
        int r = ty*2 + i;
        #pragma unroll
        for (int j=0;j<4;j++){
            int c = tx*4 + j;
            float p1 = acc5[1][i][j], p2 = acc5[2][i][j], p3 = acc5[4][i][j];
            sH[0*2048 + r*64 + c] = acc5[0][i][j];
            sH[1*2048 + r*64 + c] = p1 - p2;
            sH[2*2048 + r*64 + c] = p3 - p1 - p2;
            sH[3*2048 + r*64 + c] = acc5[3][i][j];
        }
    }
    __syncthreads();
}

// ---------------------------------------------------------------------------
// K1 = aggH + gates. grid (b=32, rt=5), 256 thr, 57344B dyn smem.
// ---------------------------------------------------------------------------
__global__ __launch_bounds__(256) void k1_aggGates(
    int t, int mask, int doAgg,
    const float* __restrict__ Hs0, const float* __restrict__ Hs1,
    const float* __restrict__ b0, const float* __restrict__ b1)
{
    extern __shared__ float sm[];
    float* stage = sm;
    float* sH = sm + 6144;
    int b = blockIdx.x, rt = blockIdx.y, tid = threadIdx.x;

    if (doAgg){
        aggTileMixed(stage, sH, rt, g_Hf + b*64, 2048, (size_t)SLOTSTR);
        for (int i=tid; i<4096; i+=256){
            int m = i >> 10; int r = (i>>5)&31; int c = i&31;
            int n = rt*32 + r;
            if (n < Nn)
                g_AH0[(size_t)m*Nn*1024 + (size_t)n*1024 + b*32 + c] = sH[m*2048 + r*64 + c];
        }
    } else {
        for (int i=tid;i<8192;i+=256) sH[i] = 0.f;
    }
    if (mask & 1){
        for (int i=tid;i<2048;i+=256){
            int m = i >> 9; int r = (i>>4)&31; int c = i&15;
            int n = rt*32 + r;
            float v = 0.f;
            if (n < Nn)
                v = g_AXt[(size_t)m*Tt*Nn*512 + (size_t)t*Nn*512 + (size_t)n*512 + b*16 + c];
            stage[m*512 + r*16 + c] = v;
        }
    }
    __syncthreads();

    int h = tid & 31, grp = tid >> 5;
    const float4* W4 = reinterpret_cast<const float4*>(g_W);
    #pragma unroll
    for (int l=0;l<2;l++){
        if (!(mask & (1<<l))) continue;
        const float4* Wz = W4 + (size_t)(l*3+0)*2048 + h;
        const float4* Wr = W4 + (size_t)(l*3+1)*2048 + h;
        const float* bias = l ? b1 : b0;
        const float* Hs = l ? Hs1 : Hs0;
        float* Z = g_Z + (size_t)l*HSZ;
        float bz[4], brr[4];
        #pragma unroll
        for (int r=0;r<4;r++){ bz[r]=bias[h*4+r]; brr[r]=bias[128+h*4+r]; }
        for (int j=0;j<4;j++){
            int nl = grp*4 + j; int n = rt*32 + nl;
            if (n >= Nn) continue;
            float yz0=0,yz1=0,yz2=0,yz3=0, yr0=0,yr1=0,yr2=0,yr3=0;
            if (l==0){
                #pragma unroll
                for (int c=0;c<16;c++){
                    float4 wz = Wz[c*32], wr = Wr[c*32];
                    float x0 =stage[0*512+nl*16+c], x1r=stage[1*512+nl*16+c],
                          x1i=stage[2*512+nl*16+c], x2 =stage[3*512+nl*16+c];
                    yz0+=x0*wz.x; yz1+=x1r*wz.y - x1i*wz.z; yz2+=x1r*wz.z + x1i*wz.y; yz3+=x2*wz.w;
                    yr0+=x0*wr.x; yr1+=x1r*wr.y - x1i*wr.z; yr2+=x1r*wr.z + x1i*wr.y; yr3+=x2*wr.w;
                }
                #pragma unroll
                for (int c=0;c<32;c++){
                    float4 wz = Wz[(16+c)*32], wr = Wr[(16+c)*32];
                    float x0 =sH[0*2048+nl*64+c], x1r=sH[1*2048+nl*64+c],
                          x1i=sH[2*2048+nl*64+c], x2 =sH[3*2048+nl*64+c];
                    yz0+=x0*wz.x; yz1+=x1r*wz.y - x1i*wz.z; yz2+=x1r*wz.z + x1i*wz.y; yz3+=x2*wz.w;
                    yr0+=x0*wr.x; yr1+=x1r*wr.y - x1i*wr.z; yr2+=x1r*wr.z + x1i*wr.y; yr3+=x2*wr.w;
                }
            } else {
                #pragma unroll
                for (int c=0;c<64;c++){
                    float4 wz = Wz[c*32], wr = Wr[c*32];
                    float x0 =sH[0*2048+nl*64+c], x1r=sH[1*2048+nl*64+c],
                          x1i=sH[2*2048+nl*64+c], x2 =sH[3*2048+nl*64+c];
                    yz0+=x0*wz.x; yz1+=x1r*wz.y - x1i*wz.z; yz2+=x1r*wz.z + x1i*wz.y; yz3+=x2*wz.w;
                    yr0+=x0*wr.x; yr1+=x1r*wr.y - x1i*wr.z; yr2+=x1r*wr.z + x1i*wr.y; yr3+=x2*wr.w;
                }
            }
            float vz[4] = {0.25f*(yz0+yz3+2.f*yz1), 0.25f*(yz0-yz3-2.f*yz2),
                           0.25f*(yz0+yz3-2.f*yz1), 0.25f*(yz0-yz3+2.f*yz2)};
            float vr[4] = {0.25f*(yr0+yr3+2.f*yr1), 0.25f*(yr0-yr3-2.f*yr2),
                           0.25f*(yr0+yr3-2.f*yr1), 0.25f*(yr0-yr3+2.f*yr2)};
            size_t hoff = (((size_t)b*Nn + n)*Hh + h)*4;
            float4 hs4 = *reinterpret_cast<const float4*>(Hs + hoff);
            float hsv[4] = {hs4.x,hs4.y,hs4.z,hs4.w};
            float g[4], zv[4];
            #pragma unroll
            for (int r=0;r<4;r++){
                zv[r] = 1.f/(1.f+expf(-(vz[r] + bz[r])));
                float rg = 1.f/(1.f+expf(-(vr[r] + brr[r])));
                g[r] = rg*hsv[r];
            }
            *reinterpret_cast<float4*>(Z + hoff) = make_float4(zv[0],zv[1],zv[2],zv[3]);
            size_t gb = (size_t)n*2048 + b*64 + l*32 + h;
            float s1 = g[0]-g[2], s2 = g[3]-g[1];
            g_Gf[0*(size_t)SLOTSTR + gb] = g[0]+g[1]+g[2]+g[3];
            g_Gf[1*(size_t)SLOTSTR + gb] = s1;
            g_Gf[2*(size_t)SLOTSTR + gb] = s2;
            g_Gf[3*(size_t)SLOTSTR + gb] = g[0]-g[1]+g[2]-g[3];
            g_Gf[4*(size_t)SLOTSTR + gb] = s1 + s2;
        }
    }
}

// ---------------------------------------------------------------------------
// K2 = aggG + ht + hidden update. grid (b=32, rt=5).
// ---------------------------------------------------------------------------
__global__ __launch_bounds__(256) void k2_aggHt(
    int t, int mask, int doAgg,
    const float* __restrict__ Hs0, const float* __restrict__ Hs1,
    const float* __restrict__ b0, const float* __restrict__ b1,
    float* __restrict__ H0w, float* __restrict__ H1w,
    float* __restrict__ outp, float* __restrict__ tailp)
{
    extern __shared__ float sm[];
    float* stage = sm;
    float* sG = sm + 6144;
    int b = blockIdx.x, rt = blockIdx.y, tid = threadIdx.x;

    if (doAgg){
        aggTileMixed(stage, sG, rt, g_Gf + b*64, 2048, (size_t)SLOTSTR);
    } else {
        for (int i=tid;i<8192;i+=256) sG[i] = 0.f;
    }
    if (mask & 1){
        for (int i=tid;i<2048;i+=256){
            int m = i >> 9; int r = (i>>4)&31; int c = i&15;
            int n = rt*32 + r;
            float v = 0.f;
            if (n < Nn)
                v = g_AXt[(size_t)m*Tt*Nn*512 + (size_t)t*Nn*512 + (size_t)n*512 + b*16 + c];
            stage[m*512 + r*16 + c] = v;
        }
    }
    if (mask & 2){
        for (int i=tid;i<4096;i+=256){
            int m = i >> 10; int r = (i>>5)&31; int c = i&31;
            int n = rt*32 + r;
            float v = 0.f;
            if (n < Nn)
                v = g_AH0[(size_t)m*Nn*1024 + (size_t)n*1024 + b*32 + c];
            stage[2048 + m*1024 + r*32 + c] = v;
        }
    }
    __syncthreads();

    int h = tid & 31, grp = tid >> 5;
    const float4* W4 = reinterpret_cast<const float4*>(g_W);
    #pragma unroll
    for (int l=0;l<2;l++){
        if (!(mask & (1<<l))) continue;
        const float4* Wh = W4 + (size_t)(l*3+2)*2048 + h;
        const float* bias = l ? b1 : b0;
        const float* Hs = l ? Hs1 : Hs0;
        const float* Z = g_Z + (size_t)l*HSZ;
        float* Hw = l ? H1w : H0w;
        int Fin = l ? 32 : 16;
        float bh[4];
        #pragma unroll
        for (int r=0;r<4;r++) bh[r] = bias[256 + h*4 + r];
        for (int j=0;j<4;j++){
            int nl = grp*4 + j; int n = rt*32 + nl;
            if (n >= Nn) continue;
            float y0=0,y1=0,y2=0,y3=0;
            if (l==0){
                #pragma unroll
                for (int c=0;c<16;c++){
                    float4 w = Wh[c*32];
                    float x0 =stage[0*512+nl*16+c], x1r=stage[1*512+nl*16+c],
                          x1i=stage[2*512+nl*16+c], x2 =stage[3*512+nl*16+c];
                    y0+=x0*w.x; y1+=x1r*w.y - x1i*w.z; y2+=x1r*w.z + x1i*w.y; y3+=x2*w.w;
                }
            } else {
                #pragma unroll
                for (int c=0;c<32;c++){
                    float4 w = Wh[c*32];
                    float x0 =stage[2048+0*1024+nl*32+c], x1r=stage[2048+1*1024+nl*32+c],
                          x1i=stage[2048+2*1024+nl*32+c], x2 =stage[2048+3*1024+nl*32+c];
                    y0+=x0*w.x; y1+=x1r*w.y - x1i*w.z; y2+=x1r*w.z + x1i*w.y; y3+=x2*w.w;
                }
            }
            #pragma unroll
            for (int c=0;c<32;c++){
                float4 w = Wh[(Fin+c)*32];
                int gc = l*32 + c;
                float x0 =sG[0*2048+nl*64+gc], x1r=sG[1*2048+nl*64+gc],
                      x1i=sG[2*2048+nl*64+gc], x2 =sG[3*2048+nl*64+gc];
                y0+=x0*w.x; y1+=x1r*w.y - x1i*w.z; y2+=x1r*w.z + x1i*w.y; y3+=x2*w.w;
            }
            float v[4] = {0.25f*(y0+y3+2.f*y1), 0.25f*(y0-y3-2.f*y2),
                          0.25f*(y0+y3-2.f*y1), 0.25f*(y0-y3+2.f*y2)};
            size_t hoff = (((size_t)b*Nn + n)*Hh + h)*4;
            float4 z4 = *reinterpret_cast<const float4*>(Z + hoff);
            float zv[4] = {z4.x,z4.y,z4.z,z4.w};
            float4 hs4 = *reinterpret_cast<const float4*>(Hs + hoff);
            float hsv[4] = {hs4.x,hs4.y,hs4.z,hs4.w};
            float hn[4];
            #pragma unroll
            for (int r=0;r<4;r++){
                float ht = tanhf(v[r] + bh[r]);
                hn[r] = zv[r]*hsv[r] + (1.f-zv[r])*ht;
            }
            float4 hv = make_float4(hn[0],hn[1],hn[2],hn[3]);
            *reinterpret_cast<float4*>(Hw + hoff) = hv;
            if (l==1 && outp)
                *reinterpret_cast<float4*>(outp + (((size_t)b*Tt + t)*Nn + n)*(Hh*4) + h*4) = hv;
            if (tailp)
                *reinterpret_cast<float4*>(tailp + (size_t)l*HSZ + hoff) = hv;
            size_t hb = (size_t)n*2048 + b*64 + l*32 + h;
            float s1 = hn[0]-hn[2], s2 = hn[3]-hn[1];
            g_Hf[0*(size_t)SLOTSTR + hb] = hn[0]+hn[1]+hn[2]+hn[3];
            g_Hf[1*(size_t)SLOTSTR + hb] = s1;
            g_Hf[2*(size_t)SLOTSTR + hb] = s2;
            g_Hf[3*(size_t)SLOTSTR + hb] = hn[0]-hn[1]+hn[2]-hn[3];
            g_Hf[4*(size_t)SLOTSTR + hb] = s1 + s2;
        }
    }
}

// ---------------------------------------------------------------------------
// Batched X aggregation (all t), mixed output.
// ---------------------------------------------------------------------------
__global__ __launch_bounds__(256) void aggx2_kernel(){
    extern __shared__ float sm[];
    float* stage = sm;
    float* sH = sm + 6144;
    int ct = blockIdx.x & 7, t = blockIdx.x >> 3, rt = blockIdx.y, tid = threadIdx.x;
    aggTileMixed(stage, sH, rt, g_Xf + (size_t)t*NP*512 + ct*64, 512, (size_t)Tt*NP*512);
    for (int i=tid; i<8192; i+=256){
        int m = i >> 11; int r = (i>>6)&31; int c = i&63;
        int n = rt*32 + r;
        if (n < Nn)
            g_AXt[(size_t)m*Tt*Nn*512 + (size_t)t*Nn*512 + (size_t)n*512 + ct*64 + c]
                = sH[m*2048 + r*64 + c];
    }
}

// ---------------------------------------------------------------------------
extern "C" void kernel_launch(void* const* d_in, const int* in_sizes, int n_in,
                              void* d_out, int out_size) {
    (void)in_sizes; (void)n_in;
    const float* inputs = (const float*)d_in[0];
    const float* U      = (const float*)d_in[1];
    const float* B0p    = (const float*)d_in[7];
    const float* B1p    = (const float*)d_in[13];
    float* out = (float*)d_out;
    const int OUTSZ = Bb*Tt*Nn*Hh*Rr;
    float* tail = (out_size >= OUTSZ + 2*HSZ) ? (out + OUTSZ) : nullptr;

    const int SMEMB = 14336*4;  // 57344 B
    cudaFuncSetAttribute(aggx2_kernel, cudaFuncAttributeMaxDynamicSharedMemorySize, SMEMB);
    cudaFuncSetAttribute(k1_aggGates, cudaFuncAttributeMaxDynamicSharedMemorySize, SMEMB);
    cudaFuncSetAttribute(k2_aggHt,    cudaFuncAttributeMaxDynamicSharedMemorySize, SMEMB);

    void* p;
    cudaGetSymbolAddress(&p, g_At);  float* Atp = (float*)p;
    cudaGetSymbolAddress(&p, g_Xf);  float* Xf  = (float*)p;
    cudaGetSymbolAddress(&p, g_Hf);  float* Hf  = (float*)p;
    cudaGetSymbolAddress(&p, g_Gf);  float* Gfp = (float*)p;
    cudaGetSymbolAddress(&p, g_H);   float* Hb  = (float*)p;

    cudaMemsetAsync(Atp, 0, sizeof(float)*5*NP*NR);
    cudaMemsetAsync(Xf,  0, sizeof(float)*5*Tt*NP*512);
    cudaMemsetAsync(Hf,  0, sizeof(float)*5*NP*2048);
    cudaMemsetAsync(Gfp, 0, sizeof(float)*5*NP*2048);
    cudaMemsetAsync(Hb,  0, sizeof(float)*4*HSZ);

    adj_kernel<<<Nn, 256>>>(U);
    wprep_kernel<<<48, 256>>>((const float*)d_in[2], (const float*)d_in[3], (const float*)d_in[4],
                              (const float*)d_in[5], (const float*)d_in[6],
                              (const float*)d_in[8], (const float*)d_in[9], (const float*)d_in[10],
                              (const float*)d_in[11], (const float*)d_in[12]);
    xprep_kernel<<<(Tt*Nn*512+255)/256, 256>>>(inputs);
    aggx2_kernel<<<dim3(64,5), 256, SMEMB>>>();

    float* H0[2] = {Hb,          Hb +   HSZ};
    float* H1[2] = {Hb + 2*HSZ,  Hb + 3*HSZ};
    dim3 grd(32,5);

    // ---- t = 0 ----
    // layer0: no H terms
    k1_aggGates<<<grd,256,SMEMB>>>(0, 1, 0, H0[0], H1[0], B0p, B1p);
    k2_aggHt   <<<grd,256,SMEMB>>>(0, 1, 0, H0[0], H1[0], B0p, B1p,
                                   H0[1], H1[1], out, nullptr);
    // layer1: consumes CURRENT H0(t0); agg of Hf (H0 cols live, H1 cols zero)
    k1_aggGates<<<grd,256,SMEMB>>>(0, 2, 1, H0[0], H1[0], B0p, B1p);
    k2_aggHt   <<<grd,256,SMEMB>>>(0, 2, 0, H0[0], H1[0], B0p, B1p,
                                   H0[1], H1[1], out, nullptr);
    int c0 = 1, c1 = 1;

    // ---- t = 1..7 ----
    for (int t=1; t<Tt; t++){
        float* tl = (t==Tt-1) ? tail : nullptr;
        k1_aggGates<<<grd,256,SMEMB>>>(t, 3, 1, H0[c0], H1[c1], B0p, B1p);
        k2_aggHt   <<<grd,256,SMEMB>>>(t, 3, 1, H0[c0], H1[c1], B0p, B1p,
                                       H0[c0^1], H1[c1^1], out, tl);
        c0 ^= 1; c1 ^= 1;
    }
}

// round 8
// speedup vs baseline: 1.4331x; 1.4331x over previous
#include <cuda_runtime.h>
#include <math.h>

#define Bb 32
#define Tt 8
#define Nn 150
#define Ff 16
#define Hh 32
#define Rr 4
#define Ee 16

#define NP 160
#define NR 192
#define JB 2560                    // agg1 col space: X(512) | H0(1024) | H1(1024)
#define JG 2048                    // agg2 col space: G0(1024) | G1(1024)
#define XT (NP*512)
#define HSZ (Bb*Nn*Hh*Rr)

// slots: 0=f0, 1=Re f1, 2=Im f1, 3=f2, 4=slot1+slot2 (Karatsuba)
__device__ float g_At  [5*NP*NR];
__device__ float g_W   [2*3*4*64*32];
__device__ float g_Xall[5*Tt*NP*512];
__device__ float g_Hf  [5*NP*2048];
__device__ float g_AXH [5*Nn*JB];
__device__ float g_Gf  [5*NP*2048];
__device__ float g_AG  [5*Nn*JG];
__device__ float g_Z   [2*HSZ];
__device__ float g_H   [4*HSZ];

// ---------------------------------------------------------------------------
__global__ void adj_kernel(const float* __restrict__ U) {
    cudaGridDependencySynchronize();
    __shared__ float sUf[Ee][4];
    __shared__ float red[256];
    int n = blockIdx.x;
    int tid = threadIdx.x;
    if (tid < Ee*4) {
        int e = tid >> 2, s = tid & 3;
        const float* p = U + (n*Ee + e)*4;
        float u0=p[0],u1=p[1],u2=p[2],u3=p[3];
        float v;
        if (s==0) v = u0+u1+u2+u3;
        else if (s==1) v = u0-u2;
        else if (s==2) v = u3-u1;
        else v = u0-u1+u2-u3;
        sUf[e][s] = v;
    }
    __syncthreads();
    int m = tid;
    float a0=0.f,a1=0.f,a2=0.f,a3=0.f;
    if (m < Nn) {
        float P0=0.f,P1r=0.f,P1i=0.f,P2=0.f;
        #pragma unroll
        for (int e=0;e<Ee;e++){
            const float* p = U + (m*Ee + e)*4;
            float u0=p[0],u1=p[1],u2=p[2],u3=p[3];
            float m0=u0+u1+u2+u3, m1r=u0-u2, m1i=u3-u1, m2=u0-u1+u2-u3;
            float q0=sUf[e][0], q1r=sUf[e][1], q1i=sUf[e][2], q2=sUf[e][3];
            P0  += q0*m0;
            P2  += q2*m2;
            P1r += q1r*m1r - q1i*m1i;
            P1i += q1r*m1i + q1i*m1r;
        }
        a0 = fmaxf(0.25f*(P0 + P2 + 2.f*P1r), 0.f);
        a1 = fmaxf(0.25f*(P0 - P2 - 2.f*P1i), 0.f);
        a2 = fmaxf(0.25f*(P0 + P2 - 2.f*P1r), 0.f);
        a3 = fmaxf(0.25f*(P0 - P2 + 2.f*P1i), 0.f);
    }
    float av[4] = {a0,a1,a2,a3};
    float v[4];
    for (int r=0;r<4;r++){
        red[tid] = (m<Nn) ? av[r] : -1e30f; __syncthreads();
        for (int s=128;s>0;s>>=1){ if (tid<s) red[tid]=fmaxf(red[tid],red[tid+s]); __syncthreads(); }
        float mx = red[0]; __syncthreads();
        float ex = (m<Nn) ? expf(av[r]-mx) : 0.f;
        red[tid] = ex; __syncthreads();
        for (int s=128;s>0;s>>=1){ if (tid<s) red[tid]+=red[tid+s]; __syncthreads(); }
        float sm = red[0]; __syncthreads();
        v[r] = ex / sm;
    }
    if (m < Nn) {
        float s1 = v[0]-v[2];
        float s2 = v[3]-v[1];
        g_At[0*NP*NR + m*NR + n] = v[0]+v[1]+v[2]+v[3];
        g_At[1*NP*NR + m*NR + n] = s1;
        g_At[2*NP*NR + m*NR + n] = s2;
        g_At[3*NP*NR + m*NR + n] = v[0]-v[1]+v[2]-v[3];
        g_At[4*NP*NR + m*NR + n] = s1 + s2;
    }
}

// ---------------------------------------------------------------------------
__global__ void wprep_kernel(const float* wxz0,const float* wxr0,const float* wxh0,
                             const float* whz0,const float* whr0,
                             const float* wxz1,const float* wxr1,const float* wxh1,
                             const float* whz1,const float* whr1) {
    cudaGridDependencySynchronize();
    int idx = blockIdx.x*blockDim.x + threadIdx.x;
    if (idx >= 2*3*64*32) return;
    int h = idx & 31;
    int c = (idx >> 5) & 63;
    int g = (idx >> 11) % 3;
    int l = idx / (3*64*32);
    int Fin = l ? 32 : 16;
    int C = Fin + 32;
    float w[4] = {0.f,0.f,0.f,0.f};
    if (c < C) {
        bool xp = c < Fin;
        int row = xp ? c : (c - Fin);
        const float* src;
        if (l == 0)
            src = (g==0) ? (xp? wxz0: whz0) : (g==1) ? (xp? wxr0: whr0) : (xp? wxh0: whr0);
        else
            src = (g==0) ? (xp? wxz1: whz1) : (g==1) ? (xp? wxr1: whr1) : (xp? wxh1: whr1);
        const float* p = src + (row*Hh + h)*4;
        float u0=p[0],u1=p[1],u2=p[2],u3=p[3];
        w[0]=u0+u1+u2+u3; w[1]=u0-u2; w[2]=u3-u1; w[3]=u0-u1+u2-u3;
    }
    int base = ((l*3+g)*4)*2048 + c*32 + h;
    #pragma unroll
    for (int s=0;s<4;s++) g_W[base + s*2048] = w[s];
}

// ---------------------------------------------------------------------------
__global__ void xprep_kernel(const float* __restrict__ X){
    cudaGridDependencySynchronize();
    int idx = blockIdx.x*blockDim.x + threadIdx.x;
    if (idx >= Tt*Nn*512) return;
    int col = idx & 511;
    int rest = idx >> 9;
    int n = rest % Nn;
    int t = rest / Nn;
    int b = col >> 4, f = col & 15;
    const float4 v = *reinterpret_cast<const float4*>(
        X + ((((size_t)b*Tt + t)*Nn + n)*Ff + f)*4);
    float s1 = v.x - v.z, s2 = v.w - v.y;
    size_t base = ((size_t)t*NP + n)*512 + col;
    const size_t SS = (size_t)Tt*NP*512;
    g_Xall[0*SS + base] = v.x+v.y+v.z+v.w;
    g_Xall[1*SS + base] = s1;
    g_Xall[2*SS + base] = s2;
    g_Xall[3*SS + base] = v.x-v.y+v.z-v.w;
    g_Xall[4*SS + base] = s1 + s2;
}

// ---------------------------------------------------------------------------
// Aggregation GEMM (identical hot loop to the 1075us version).
// ---------------------------------------------------------------------------
__global__ __launch_bounds__(256) void agg4_kernel(
    const float* __restrict__ B0, int ld0, size_t sst0, int xlim,
    const float* __restrict__ B1, int ld1, size_t sst1,
    float* __restrict__ Out, int ldo, size_t ssto, int bxOff)
{
    cudaGridDependencySynchronize();
    int s = blockIdx.z;
    int colG = (bxOff + blockIdx.x)*128;
    const float* Bp; int ld; size_t sst; int colL;
    if (colG < xlim){ Bp=B0; ld=ld0; sst=sst0; colL=colG; }
    else            { Bp=B1; ld=ld1; sst=sst1; colL=colG-xlim; }
    const float* A = g_At + (size_t)s*NP*NR;
    const float* X = Bp + s*sst + colL;
    float* O = Out + s*ssto + colG;
    int nBase = blockIdx.y*64;

    __shared__ float sA[2][16][64];
    __shared__ float sB[2][16][128];
    int tx=threadIdx.x, ty=threadIdx.y, tid=ty*32+tx;

    int ak = tid>>4, an = (tid&15)*4;
    int bk = tid>>5, bc = (tid&31)*4;
    const float* Ap = A + (size_t)ak*NR + nBase + an;
    const float* Bq = X + (size_t)bk*ld + bc;

    float4 ra, rb0, rb1;
    ra  = *reinterpret_cast<const float4*>(Ap);
    rb0 = *reinterpret_cast<const float4*>(Bq);
    rb1 = *reinterpret_cast<const float4*>(Bq + 8*(size_t)ld);
    *reinterpret_cast<float4*>(&sA[0][ak][an]) = ra;
    *reinterpret_cast<float4*>(&sB[0][bk][bc]) = rb0;
    *reinterpret_cast<float4*>(&sB[0][8+bk][bc]) = rb1;
    __syncthreads();

    float acc[2][4][4] = {};
    for (int ch=0; ch<10; ch++){
        int buf = ch&1;
        if (ch<9){
            size_t ko = (size_t)(ch+1)*16;
            ra  = *reinterpret_cast<const float4*>(Ap + ko*NR);
            rb0 = *reinterpret_cast<const float4*>(Bq + ko*ld);
            rb1 = *reinterpret_cast<const float4*>(Bq + (ko+8)*ld);
        }
        #pragma unroll
        for (int kk=0;kk<16;kk++){
            float4 a0 = *reinterpret_cast<const float4*>(&sA[buf][kk][ty*4]);
            float4 a1 = *reinterpret_cast<const float4*>(&sA[buf][kk][32+ty*4]);
            float4 b  = *reinterpret_cast<const float4*>(&sB[buf][kk][tx*4]);
            float aa0[4]={a0.x,a0.y,a0.z,a0.w};
            float aa1[4]={a1.x,a1.y,a1.z,a1.w};
            float bv[4]={b.x,b.y,b.z,b.w};
            #pragma unroll
            for (int i=0;i<4;i++){
                #pragma unroll
                for (int j=0;j<4;j++){
                    acc[0][i][j] += aa0[i]*bv[j];
                    acc[1][i][j] += aa1[i]*bv[j];
                }
            }
        }
        if (ch<9){
            int nb = buf^1;
            *reinterpret_cast<float4*>(&sA[nb][ak][an]) = ra;
            *reinterpret_cast<float4*>(&sB[nb][bk][bc]) = rb0;
            *reinterpret_cast<float4*>(&sB[nb][8+bk][bc]) = rb1;
        }
        __syncthreads();
    }
    #pragma unroll
    for (int ri=0; ri<2; ri++){
        #pragma unroll
        for (int i=0;i<4;i++){
            int n = nBase + ri*32 + ty*4 + i;
            if (n < Nn)
                *reinterpret_cast<float4*>(O + (size_t)n*ldo + tx*4) =
                    make_float4(acc[ri][i][0],acc[ri][i][1],acc[ri][i][2],acc[ri][i][3]);
        }
    }
}

// ---------------------------------------------------------------------------
__global__ void gates4_kernel(int secBase,
    const float* __restrict__ HsA, const float* __restrict__ biasA,
    const float* __restrict__ HsB, const float* __restrict__ biasB)
{
    cudaGridDependencySynchronize();
    int n = blockIdx.x;
    int sec = secBase + blockIdx.y;
    const float* Hs   = blockIdx.y ? HsB : HsA;
    const float* bias = blockIdx.y ? biasB : biasA;
    int C    = sec ? 64 : 48;
    int wb   = sec ? 3*8192 : 0;
    int gcol = sec ? 1024 : 0;

    __shared__ float sX[4][64][33];
    int tid = threadIdx.y*32 + threadIdx.x;
    const size_t SS = (size_t)Nn*JB;
    const float* AX = g_AXH + (size_t)n*JB;
    int colBase = sec ? 1536 : 0;
    (void)colBase;
    for (int i=tid;i<4*C*32;i+=128){
        int c = i % C; int sb = i / C; int s = sb >> 5; int b = sb & 31;
        int col = (sec==0) ? ((c<16)?(b*16+c):(512 + b*32 + (c-16)))
                           : ((c<32)?(512 + b*32 + c):(1536 + b*32 + (c-32)));
        float v;
        if (s==0)      v = AX[col];
        else if (s==1) v = AX[SS+col] - AX[2*SS+col];
        else if (s==2) v = AX[4*SS+col] - AX[SS+col] - AX[2*SS+col];
        else           v = AX[3*SS+col];
        sX[s][c][b] = v;
    }
    __syncthreads();

    int h = threadIdx.x, bt = threadIdx.y;
    const float* Wz = g_W + wb;
    const float* Wr = Wz + 4*2048;
    float yz0[8]={},yz1[8]={},yz2[8]={},yz3[8]={};
    float yr0[8]={},yr1[8]={},yr2[8]={},yr3[8]={};
    for (int c=0;c<C;c++){
        int wo = c*32 + h;
        float wz0=Wz[wo],wz1=Wz[2048+wo],wz2=Wz[4096+wo],wz3=Wz[6144+wo];
        float wr0=Wr[wo],wr1=Wr[2048+wo],wr2=Wr[4096+wo],wr3=Wr[6144+wo];
        #pragma unroll
        for (int bb=0;bb<8;bb++){
            int b = bt*8+bb;
            float x0=sX[0][c][b], x1r=sX[1][c][b], x1i=sX[2][c][b], x2=sX[3][c][b];
            yz0[bb] += x0*wz0;
            yz1[bb] += x1r*wz1 - x1i*wz2;
            yz2[bb] += x1r*wz2 + x1i*wz1;
            yz3[bb] += x2*wz3;
            yr0[bb] += x0*wr0;
            yr1[bb] += x1r*wr1 - x1i*wr2;
            yr2[bb] += x1r*wr2 + x1i*wr1;
            yr3[bb] += x2*wr3;
        }
    }
    float bz[4], br[4];
    #pragma unroll
    for (int r=0;r<4;r++){ bz[r]=bias[h*4+r]; br[r]=bias[128+h*4+r]; }
    float* Z = g_Z + (size_t)sec*HSZ;
    const size_t GS = (size_t)NP*2048;
    #pragma unroll
    for (int bb=0;bb<8;bb++){
        int b = bt*8+bb;
        float vz[4] = {0.25f*(yz0[bb]+yz3[bb]+2.f*yz1[bb]), 0.25f*(yz0[bb]-yz3[bb]-2.f*yz2[bb]),
                       0.25f*(yz0[bb]+yz3[bb]-2.f*yz1[bb]), 0.25f*(yz0[bb]-yz3[bb]+2.f*yz2[bb])};
        float vr[4] = {0.25f*(yr0[bb]+yr3[bb]+2.f*yr1[bb]), 0.25f*(yr0[bb]-yr3[bb]-2.f*yr2[bb]),
                       0.25f*(yr0[bb]+yr3[bb]-2.f*yr1[bb]), 0.25f*(yr0[bb]-yr3[bb]+2.f*yr2[bb])};
        size_t hoff = (((size_t)b*Nn + n)*Hh + h)*4;
        float4 hs4 = Hs ? *reinterpret_cast<const float4*>(Hs + hoff) : make_float4(0,0,0,0);
        float hsv[4] = {hs4.x,hs4.y,hs4.z,hs4.w};
        float g[4], zv[4];
        #pragma unroll
        for (int r=0;r<4;r++){
            zv[r] = 1.f/(1.f+expf(-(vz[r] + bz[r])));
            float rg = 1.f/(1.f+expf(-(vr[r] + br[r])));
            g[r] = rg*hsv[r];
        }
        *reinterpret_cast<float4*>(Z + hoff) = make_float4(zv[0],zv[1],zv[2],zv[3]);
        size_t gb = (size_t)n*2048 + gcol + b*Hh + h;
        float s1 = g[0]-g[2], s2 = g[3]-g[1];
        g_Gf[0*GS + gb] = g[0]+g[1]+g[2]+g[3];
        g_Gf[1*GS + gb] = s1;
        g_Gf[2*GS + gb] = s2;
        g_Gf[3*GS + gb] = g[0]-g[1]+g[2]-g[3];
        g_Gf[4*GS + gb] = s1 + s2;
    }
}

// ---------------------------------------------------------------------------
__global__ void ht4_kernel(int secBase, int t,
    const float* __restrict__ HsA, const float* __restrict__ biasA,
    float* __restrict__ HnewA, float* __restrict__ outA, float* __restrict__ tailA,
    const float* __restrict__ HsB, const float* __restrict__ biasB,
    float* __restrict__ HnewB, float* __restrict__ outB, float* __restrict__ tailB)
{
    cudaGridDependencySynchronize();
    int n = blockIdx.x;
    int sec = secBase + blockIdx.y;
    const float* Hs   = blockIdx.y ? HsB : HsA;
    const float* bias = blockIdx.y ? biasB : biasA;
    float* Hnew = blockIdx.y ? HnewB : HnewA;
    float* outp = blockIdx.y ? outB : outA;
    float* tailp= blockIdx.y ? tailB : tailA;
    int Fin  = sec ? 32 : 16;
    int wb   = sec ? 5*8192 : 2*8192;
    int gcol = sec ? 1024 : 0;
    int hbase= sec ? 1024 : 0;

    __shared__ float sXx[4][32][33];
    __shared__ float sG[4][32][33];
    int tid = threadIdx.y*32 + threadIdx.x;
    const size_t SS = (size_t)Nn*JB;
    const size_t AS = (size_t)Nn*JG;
    const float* AX = g_AXH + (size_t)n*JB;
    const float* AG = g_AG + (size_t)n*JG + gcol;
    for (int i=tid;i<4*Fin*32;i+=128){
        int c = i % Fin; int sb = i / Fin; int s = sb >> 5; int b = sb & 31;
        int col = (sec==0) ? (b*16+c) : (512 + b*32 + c);
        float v;
        if (s==0)      v = AX[col];
        else if (s==1) v = AX[SS+col] - AX[2*SS+col];
        else if (s==2) v = AX[4*SS+col] - AX[SS+col] - AX[2*SS+col];
        else           v = AX[3*SS+col];
        sXx[s][c][b] = v;
    }
    for (int i=tid;i<4*32*32;i+=128){
        int c = i & 31; int sb = i >> 5; int s = sb >> 5; int b = sb & 31;
        int col = b*Hh + c;
        float v;
        if (s==0)      v = AG[col];
        else if (s==1) v = AG[AS+col] - AG[2*AS+col];
        else if (s==2) v = AG[4*AS+col] - AG[AS+col] - AG[2*AS+col];
        else           v = AG[3*AS+col];
        sG[s][c][b] = v;
    }
    __syncthreads();

    int h = threadIdx.x, bt = threadIdx.y;
    const float* Wh = g_W + wb;
    float y0[8]={},y1[8]={},y2[8]={},y3[8]={};
    for (int c=0;c<Fin;c++){
        int wo = c*32 + h;
        float w0=Wh[wo],w1=Wh[2048+wo],w2=Wh[4096+wo],w3=Wh[6144+wo];
        #pragma unroll
        for (int bb=0;bb<8;bb++){
            int b = bt*8+bb;
            float x0=sXx[0][c][b], x1r=sXx[1][c][b], x1i=sXx[2][c][b], x2=sXx[3][c][b];
            y0[bb] += x0*w0;
            y1[bb] += x1r*w1 - x1i*w2;
            y2[bb] += x1r*w2 + x1i*w1;
            y3[bb] += x2*w3;
        }
    }
    for (int c=0;c<Hh;c++){
        int wo = (Fin+c)*32 + h;
        float w0=Wh[wo],w1=Wh[2048+wo],w2=Wh[4096+wo],w3=Wh[6144+wo];
        #pragma unroll
        for (int bb=0;bb<8;bb++){
            int b = bt*8+bb;
            float x0=sG[0][c][b], x1r=sG[1][c][b], x1i=sG[2][c][b], x2=sG[3][c][b];
            y0[bb] += x0*w0;
            y1[bb] += x1r*w1 - x1i*w2;
            y2[bb] += x1r*w2 + x1i*w1;
            y3[bb] += x2*w3;
        }
    }
    float bh[4];
    #pragma unroll
    for (int r=0;r<4;r++) bh[r] = bias[256 + h*4 + r];
    const float* Z = g_Z + (size_t)sec*HSZ;
    const size_t HS2 = (size_t)NP*2048;
    #pragma unroll
    for (int bb=0;bb<8;bb++){
        int b = bt*8+bb;
        float v[4] = {0.25f*(y0[bb]+y3[bb]+2.f*y1[bb]), 0.25f*(y0[bb]-y3[bb]-2.f*y2[bb]),
                      0.25f*(y0[bb]+y3[bb]-2.f*y1[bb]), 0.25f*(y0[bb]-y3[bb]+2.f*y2[bb])};
        size_t hoff = (((size_t)b*Nn+n)*Hh + h)*4;
        float4 z4 = *reinterpret_cast<const float4*>(Z + hoff);
        float zv[4] = {z4.x,z4.y,z4.z,z4.w};
        float4 hs4 = Hs ? *reinterpret_cast<const float4*>(Hs + hoff) : make_float4(0,0,0,0);
        float hsv[4] = {hs4.x,hs4.y,hs4.z,hs4.w};
        float hn[4];
        #pragma unroll
        for (int r=0;r<4;r++){
            float ht = tanhf(v[r] + bh[r]);
            hn[r] = zv[r]*hsv[r] + (1.f-zv[r])*ht;
        }
        float4 hv = make_float4(hn[0],hn[1],hn[2],hn[3]);
        *reinterpret_cast<float4*>(Hnew + hoff) = hv;
        if (outp)
            *reinterpret_cast<float4*>(outp + (((size_t)b*Tt + t)*Nn + n)*(Hh*4) + h*4) = hv;
        if (tailp)
            *reinterpret_cast<float4*>(tailp + hoff) = hv;
        size_t hb = (size_t)n*2048 + hbase + b*Hh + h;
        float s1 = hn[0]-hn[2], s2 = hn[3]-hn[1];
        g_Hf[0*HS2 + hb] = hn[0]+hn[1]+hn[2]+hn[3];
        g_Hf[1*HS2 + hb] = s1;
        g_Hf[2*HS2 + hb] = s2;
        g_Hf[3*HS2 + hb] = hn[0]-hn[1]+hn[2]-hn[3];
        g_Hf[4*HS2 + hb] = s1 + s2;
    }
}

// ---------------------------------------------------------------------------
// PDL launch helper: every kernel in the chain launches early and waits on its
// predecessor via cudaGridDependencySynchronize() -> launch gaps collapse.
// ---------------------------------------------------------------------------
template <typename K, typename... Args>
static inline void pdl(K kern, dim3 g, dim3 b, Args... args){
    cudaLaunchConfig_t cfg = {};
    cfg.gridDim = g;
    cfg.blockDim = b;
    cfg.dynamicSmemBytes = 0;
    cfg.stream = 0;
    cudaLaunchAttribute attr[1];
    attr[0].id = cudaLaunchAttributeProgrammaticStreamSerialization;
    attr[0].val.programmaticStreamSerializationAllowed = 1;
    cfg.attrs = attr;
    cfg.numAttrs = 1;
    cudaLaunchKernelEx(&cfg, kern, args...);
}

// ---------------------------------------------------------------------------
extern "C" void kernel_launch(void* const* d_in, const int* in_sizes, int n_in,
                              void* d_out, int out_size) {
    (void)in_sizes; (void)n_in;
    const float* inputs = (const float*)d_in[0];
    const float* U      = (const float*)d_in[1];
    const float* B0p    = (const float*)d_in[7];
    const float* B1p    = (const float*)d_in[13];
    float* out = (float*)d_out;
    const int OUTSZ = Bb*Tt*Nn*Hh*Rr;
    float* tail = (out_size >= OUTSZ + 2*HSZ) ? (out + OUTSZ) : nullptr;

    void* p;
    cudaGetSymbolAddress(&p, g_At);   float* Atp  = (float*)p;
    cudaGetSymbolAddress(&p, g_Xall); float* Xall = (float*)p;
    cudaGetSymbolAddress(&p, g_Hf);   float* Hf   = (float*)p;
    cudaGetSymbolAddress(&p, g_AXH);  float* AXH  = (float*)p;
    cudaGetSymbolAddress(&p, g_Gf);   float* Gfp  = (float*)p;
    cudaGetSymbolAddress(&p, g_AG);   float* AG   = (float*)p;
    cudaGetSymbolAddress(&p, g_H);    float* Hb   = (float*)p;
    float* H0[2] = {Hb,          Hb +   HSZ};
    float* H1[2] = {Hb + 2*HSZ,  Hb + 3*HSZ};

    cudaMemsetAsync(Atp,  0, sizeof(float)*5*NP*NR);
    cudaMemsetAsync(Xall, 0, sizeof(float)*5*Tt*NP*512);
    cudaMemsetAsync(Hf,   0, sizeof(float)*5*NP*2048);
    cudaMemsetAsync(Gfp,  0, sizeof(float)*5*NP*2048);
    cudaMemsetAsync(AG,   0, sizeof(float)*5*Nn*JG);
    cudaMemsetAsync(AXH,  0, sizeof(float)*5*Nn*JB);

    pdl(adj_kernel, dim3(Nn), dim3(256), U);
    pdl(wprep_kernel, dim3(48), dim3(256),
        (const float*)d_in[2], (const float*)d_in[3], (const float*)d_in[4],
        (const float*)d_in[5], (const float*)d_in[6],
        (const float*)d_in[8], (const float*)d_in[9], (const float*)d_in[10],
        (const float*)d_in[11], (const float*)d_in[12]);
    pdl(xprep_kernel, dim3((Tt*Nn*512+255)/256), dim3(256), inputs);

    const size_t XSST = (size_t)Tt*XT;
    const size_t HSST = (size_t)NP*2048;
    const size_t AXS  = (size_t)Nn*JB;
    const size_t AGS  = (size_t)Nn*JG;
    dim3 blk128(32,4);
    dim3 aggT(32,8);

    // ---- t = 0, layer0 (H cols of AXH zero via memset) ----
    pdl(agg4_kernel, dim3(4,3,5), aggT,
        (const float*)Xall, 512, XSST, 512, (const float*)Hf, (int)JG, HSST,
        AXH, (int)JB, AXS, 0);
    pdl(gates4_kernel, dim3(Nn,1), blk128,
        0, (const float*)nullptr, B0p, (const float*)nullptr, B0p);
    pdl(ht4_kernel, dim3(Nn,1), blk128,
        0, 0,
        (const float*)nullptr, B0p, H0[1], (float*)nullptr, (float*)nullptr,
        (const float*)nullptr, B0p, H0[1], (float*)nullptr, (float*)nullptr);
    // A @ fft(H0(t0)) for layer1's t0 input
    pdl(agg4_kernel, dim3(8,3,5), aggT,
        (const float*)Xall, 512, XSST, 512, (const float*)Hf, (int)JG, HSST,
        AXH, (int)JB, AXS, 4);
    pdl(gates4_kernel, dim3(Nn,1), blk128,
        1, (const float*)nullptr, B1p, (const float*)nullptr, B1p);
    pdl(ht4_kernel, dim3(Nn,1), blk128,
        1, 0,
        (const float*)nullptr, B1p, H1[1], out, (float*)nullptr,
        (const float*)nullptr, B1p, H1[1], out, (float*)nullptr);

    // ---- t = 1..7 ----
    int c0 = 1, c1 = 1;
    for (int t=1; t<Tt; t++){
        float* tl0 = (t==Tt-1 && tail) ? tail        : nullptr;
        float* tl1 = (t==Tt-1 && tail) ? tail + HSZ  : nullptr;
        const float* Xt = Xall + (size_t)t*XT;
        pdl(agg4_kernel, dim3(20,3,5), aggT,
            Xt, 512, XSST, 512, (const float*)Hf, (int)JG, HSST,
            AXH, (int)JB, AXS, 0);
        pdl(gates4_kernel, dim3(Nn,2), blk128,
            0, (const float*)H0[c0], B0p, (const float*)H1[c1], B1p);
        pdl(agg4_kernel, dim3(16,3,5), aggT,
            (const float*)Gfp, (int)JG, HSST, (1<<30), (const float*)Gfp, (int)JG, HSST,
            AG, (int)JG, AGS, 0);
        pdl(ht4_kernel, dim3(Nn,2), blk128,
            0, t,
            (const float*)H0[c0], B0p, H0[c0^1], (float*)nullptr, tl0,
            (const float*)H1[c1], B1p, H1[c1^1], out,             tl1);
        c0 ^= 1; c1 ^= 1;
    }
}